// round 7
// baseline (speedup 1.0000x reference)
#include <cuda_runtime.h>
#include <cuda_bf16.h>

// Problem constants
#define T_STEPS 1000
#define T_MAIN  990
#define BATCH   256
#define HID     512
#define NIN     3
#define NOUT    2
#define BH      (BATCH * HID)             // 131072
#define SPK_ELEMS ((size_t)T_STEPS * BH)  // 131,072,000

#define BETA    0.8f
#define THRESH  1.0f

#define NBLK    148        // one block per SM
#define NWARP   7          // warps per block
#define NJOBS   1024       // 256 b x 4 h-quads; warp-job = (b, 128-h strip)

// per-warp readout partials: [NJOBS][20]
__device__ float g_partials[NJOBS * 20];

// ---------------------------------------------------------------------------
// Kernel A: balanced scan. 148 blocks x 224 threads, no block-level barriers.
// Warp w of block k owns job wj = w*148 + k (valid if wj < 1024):
//   b = wj >> 2,  quad = wj & 3,  lanes own h = quad*128 + lane*4 (STG.128).
// x[t,b,:] read via broadcast __ldg (12KB/warp, L1-resident).
// Tail steps [990,1000) also accumulate spk.W2 partials, reduced warp-wide
// and written to g_partials.
// ---------------------------------------------------------------------------
__global__ __launch_bounds__(NWARP * 32)
void snn_scan_kernel(const float* __restrict__ x,     // [T, B, 3]
                     const float* __restrict__ W1,    // [512, 3]
                     const float* __restrict__ W2,    // [2, 512]
                     float* __restrict__ spk_out)     // [T, B, 512]
{
    const int tid  = threadIdx.x;
    const int lane = tid & 31;
    const int w    = tid >> 5;
    const int wj   = w * NBLK + blockIdx.x;
    if (wj >= NJOBS) return;

    const int b    = wj >> 2;
    const int quad = wj & 3;
    const int h0   = quad * 128 + lane * 4;

    // W1 rows for 4 owned hidden units (12 contiguous floats, 16B aligned)
    const float4 w1a = reinterpret_cast<const float4*>(W1 + h0 * 3)[0];
    const float4 w1b = reinterpret_cast<const float4*>(W1 + h0 * 3)[1];
    const float4 w1c = reinterpret_cast<const float4*>(W1 + h0 * 3)[2];
    const float wA0 = w1a.x, wA1 = w1a.y, wA2 = w1a.z;
    const float wB0 = w1a.w, wB1 = w1b.x, wB2 = w1b.y;
    const float wC0 = w1b.z, wC1 = w1b.w, wC2 = w1c.x;
    const float wD0 = w1c.y, wD1 = w1c.z, wD2 = w1c.w;

    const float* __restrict__ xb = x + b * NIN;        // x[t, b, :] at xb + t*768
    float4* __restrict__ out = reinterpret_cast<float4*>(spk_out + (size_t)b * HID + h0);

    float m0 = 0.0f, m1 = 0.0f, m2 = 0.0f, m3 = 0.0f;
    bool  p0 = false, p1 = false, p2 = false, p3 = false;  // carried reset preds

    // ---- main scan ----
    #pragma unroll 4
    for (int t = 0; t < T_MAIN; ++t) {
        const float x0 = __ldg(xb + t * (BATCH * NIN) + 0);
        const float x1 = __ldg(xb + t * (BATCH * NIN) + 1);
        const float x2 = __ldg(xb + t * (BATCH * NIN) + 2);
        const float c0 = fmaf(x2, wA2, fmaf(x1, wA1, x0 * wA0));
        const float c1 = fmaf(x2, wB2, fmaf(x1, wB1, x0 * wB0));
        const float c2 = fmaf(x2, wC2, fmaf(x1, wC1, x0 * wC0));
        const float c3 = fmaf(x2, wD2, fmaf(x1, wD1, x0 * wD0));
        // exact snn semantics: mem_new = (beta*mem + cur) * (1 - reset_prev)
        m0 = p0 ? 0.0f : fmaf(BETA, m0, c0);
        m1 = p1 ? 0.0f : fmaf(BETA, m1, c1);
        m2 = p2 ? 0.0f : fmaf(BETA, m2, c2);
        m3 = p3 ? 0.0f : fmaf(BETA, m3, c3);
        p0 = m0 > THRESH; p1 = m1 > THRESH;
        p2 = m2 > THRESH; p3 = m3 > THRESH;
        float4 sp;
        sp.x = p0 ? 1.0f : 0.0f;
        sp.y = p1 ? 1.0f : 0.0f;
        sp.z = p2 ? 1.0f : 0.0f;
        sp.w = p3 ? 1.0f : 0.0f;
        __stcs(out + (size_t)t * (BH / 4), sp);   // streaming STG.128
    }

    // ---- tail: store spikes + accumulate readout partials ----
    const float4 w2o0 = reinterpret_cast<const float4*>(W2 + h0)[0];
    const float4 w2o1 = reinterpret_cast<const float4*>(W2 + HID + h0)[0];
    float acc[20];

    #pragma unroll
    for (int k = 0; k < 10; ++k) {
        const int t = T_MAIN + k;
        const float x0 = __ldg(xb + t * (BATCH * NIN) + 0);
        const float x1 = __ldg(xb + t * (BATCH * NIN) + 1);
        const float x2 = __ldg(xb + t * (BATCH * NIN) + 2);
        const float c0 = fmaf(x2, wA2, fmaf(x1, wA1, x0 * wA0));
        const float c1 = fmaf(x2, wB2, fmaf(x1, wB1, x0 * wB0));
        const float c2 = fmaf(x2, wC2, fmaf(x1, wC1, x0 * wC0));
        const float c3 = fmaf(x2, wD2, fmaf(x1, wD1, x0 * wD0));
        m0 = p0 ? 0.0f : fmaf(BETA, m0, c0);
        m1 = p1 ? 0.0f : fmaf(BETA, m1, c1);
        m2 = p2 ? 0.0f : fmaf(BETA, m2, c2);
        m3 = p3 ? 0.0f : fmaf(BETA, m3, c3);
        p0 = m0 > THRESH; p1 = m1 > THRESH;
        p2 = m2 > THRESH; p3 = m3 > THRESH;
        float4 sp;
        sp.x = p0 ? 1.0f : 0.0f;
        sp.y = p1 ? 1.0f : 0.0f;
        sp.z = p2 ? 1.0f : 0.0f;
        sp.w = p3 ? 1.0f : 0.0f;
        __stcs(out + (size_t)t * (BH / 4), sp);

        float q0 = sp.x * w2o0.x; q0 = fmaf(sp.y, w2o0.y, q0);
        q0 = fmaf(sp.z, w2o0.z, q0); q0 = fmaf(sp.w, w2o0.w, q0);
        float q1 = sp.x * w2o1.x; q1 = fmaf(sp.y, w2o1.y, q1);
        q1 = fmaf(sp.z, w2o1.z, q1); q1 = fmaf(sp.w, w2o1.w, q1);
        acc[2 * k + 0] = q0;
        acc[2 * k + 1] = q1;
    }

    // warp-level reduce each of the 20 partials, lane0 writes scratch
    #pragma unroll
    for (int j = 0; j < 20; ++j) {
        #pragma unroll
        for (int off = 16; off > 0; off >>= 1)
            acc[j] += __shfl_xor_sync(0xFFFFFFFFu, acc[j], off);
    }
    if (lane == 0) {
        #pragma unroll
        for (int j = 0; j < 20; ++j) g_partials[wj * 20 + j] = acc[j];
    }
}

// ---------------------------------------------------------------------------
// Kernel B: finish the readout. 2 blocks x 128 threads; thread owns one b.
// Sums the 4 quad-partials per (t,o), sigmoid per t, mean over 10.
// Deterministic fixed-order sums. ~80KB of L2 reads.
// ---------------------------------------------------------------------------
__global__ __launch_bounds__(128)
void snn_readout_kernel(float* __restrict__ avg_out)   // [B, 2]
{
    const int b = blockIdx.x * 128 + threadIdx.x;
    if (b >= BATCH) return;

    float tot[20];
    #pragma unroll
    for (int j = 0; j < 20; ++j) {
        float s = 0.0f;
        #pragma unroll
        for (int q = 0; q < 4; ++q)
            s += g_partials[(4 * b + q) * 20 + j];
        tot[j] = s;
    }
    #pragma unroll
    for (int o = 0; o < NOUT; ++o) {
        float s = 0.0f;
        #pragma unroll
        for (int k = 0; k < 10; ++k)
            s += 1.0f / (1.0f + expf(-tot[2 * k + o]));
        avg_out[b * NOUT + o] = s * 0.1f;
    }
}

// ---------------------------------------------------------------------------
extern "C" void kernel_launch(void* const* d_in, const int* in_sizes, int n_in,
                              void* d_out, int out_size)
{
    const float* x  = (const float*)d_in[0];   // [1000, 256, 3]
    const float* W1 = (const float*)d_in[1];   // [512, 3]
    const float* W2 = (const float*)d_in[2];   // [2, 512]
    float* out = (float*)d_out;

    float* spk_out = out;                      // 131,072,000 floats
    float* avg_out = out + SPK_ELEMS;          // 512 floats

    snn_scan_kernel<<<NBLK, NWARP * 32>>>(x, W1, W2, spk_out);
    snn_readout_kernel<<<2, 128>>>(avg_out);
}

// round 8
// speedup vs baseline: 1.1090x; 1.1090x over previous
#include <cuda_runtime.h>
#include <cuda_bf16.h>

// Problem constants
#define T_STEPS 1000
#define T_MAIN  990
#define BATCH   256
#define HID     512
#define NIN     3
#define NOUT    2
#define BH      (BATCH * HID)             // 131072
#define SPK_ELEMS ((size_t)T_STEPS * BH)  // 131,072,000

#define BETA    0.8f
#define THRESH  1.0f

#define NJOBS   1024       // 256 b x 4 h-quads; one warp-block per job

// per-job readout partials: [NJOBS][20]
__device__ float g_partials[NJOBS * 20];

// ---------------------------------------------------------------------------
// Kernel A: scan. 1024 blocks x 32 threads (one warp per block) -> 98.8% SM
// fill (136 SMs x 7 blocks + 12 x 6). Block j = (b = j>>2, quad = j&3); lane
// owns h = quad*128 + lane*4 (STG.128 spike stores). x[:, b, :] is staged in
// this block's shared memory (float4-padded rows) so the main loop does one
// broadcast LDS.128 per step on the smem pipe — stores keep the L1tex/LSU
// path to themselves.
// ---------------------------------------------------------------------------
__global__ __launch_bounds__(32)
void snn_scan_kernel(const float* __restrict__ x,     // [T, B, 3]
                     const float* __restrict__ W1,    // [512, 3]
                     const float* __restrict__ W2,    // [2, 512]
                     float* __restrict__ spk_out)     // [T, B, 512]
{
    __shared__ float sx[T_STEPS * 4];   // 16 KB, x rows padded 3 -> 4

    const int wj   = blockIdx.x;
    const int lane = threadIdx.x;
    const int b    = wj >> 2;
    const int quad = wj & 3;
    const int h0   = quad * 128 + lane * 4;

    // Stage x[:, b, :] into shared (3000 scalar loads over 32 lanes, MLP-rich)
    #pragma unroll 4
    for (int idx = lane; idx < T_STEPS * NIN; idx += 32) {
        const int t = idx / 3;
        const int i = idx - t * 3;
        sx[t * 4 + i] = __ldg(x + (size_t)t * (BATCH * NIN) + b * NIN + i);
    }
    __syncthreads();

    // W1 rows for the 4 owned hidden units (12 contiguous floats, 16B aligned)
    const float4 w1a = reinterpret_cast<const float4*>(W1 + h0 * 3)[0];
    const float4 w1b = reinterpret_cast<const float4*>(W1 + h0 * 3)[1];
    const float4 w1c = reinterpret_cast<const float4*>(W1 + h0 * 3)[2];
    const float wA0 = w1a.x, wA1 = w1a.y, wA2 = w1a.z;
    const float wB0 = w1a.w, wB1 = w1b.x, wB2 = w1b.y;
    const float wC0 = w1b.z, wC1 = w1b.w, wC2 = w1c.x;
    const float wD0 = w1c.y, wD1 = w1c.z, wD2 = w1c.w;

    const float4* __restrict__ sx4 = reinterpret_cast<const float4*>(sx);
    float4* __restrict__ out = reinterpret_cast<float4*>(spk_out + (size_t)b * HID + h0);

    float m0 = 0.0f, m1 = 0.0f, m2 = 0.0f, m3 = 0.0f;
    bool  p0 = false, p1 = false, p2 = false, p3 = false;  // reset preds (prev mem)

    // ---- main scan ----
    #pragma unroll 2
    for (int t = 0; t < T_MAIN; ++t) {
        const float4 xv = sx4[t];
        const float c0 = fmaf(xv.z, wA2, fmaf(xv.y, wA1, xv.x * wA0));
        const float c1 = fmaf(xv.z, wB2, fmaf(xv.y, wB1, xv.x * wB0));
        const float c2 = fmaf(xv.z, wC2, fmaf(xv.y, wC1, xv.x * wC0));
        const float c3 = fmaf(xv.z, wD2, fmaf(xv.y, wD1, xv.x * wD0));
        // exact snn zero-reset: mem_new = (beta*mem + cur) * (1 - reset_prev)
        m0 = p0 ? c0 : fmaf(BETA, m0, c0);   // note: reset -> mem=0 -> beta*0+cur = cur... 
        m1 = p1 ? c1 : fmaf(BETA, m1, c1);
        m2 = p2 ? c2 : fmaf(BETA, m2, c2);
        m3 = p3 ? c3 : fmaf(BETA, m3, c3);
        p0 = m0 > THRESH; p1 = m1 > THRESH;
        p2 = m2 > THRESH; p3 = m3 > THRESH;
        float4 sp;
        sp.x = p0 ? 1.0f : 0.0f;
        sp.y = p1 ? 1.0f : 0.0f;
        sp.z = p2 ? 1.0f : 0.0f;
        sp.w = p3 ? 1.0f : 0.0f;
        __stcs(out + (size_t)t * (BH / 4), sp);   // streaming STG.128
    }

    // ---- tail: t in [990, 1000): store spikes + accumulate readout ----
    const float4 w2o0 = reinterpret_cast<const float4*>(W2 + h0)[0];
    const float4 w2o1 = reinterpret_cast<const float4*>(W2 + HID + h0)[0];
    float acc[20];

    #pragma unroll
    for (int k = 0; k < 10; ++k) {
        const int t = T_MAIN + k;
        const float4 xv = sx4[t];
        const float c0 = fmaf(xv.z, wA2, fmaf(xv.y, wA1, xv.x * wA0));
        const float c1 = fmaf(xv.z, wB2, fmaf(xv.y, wB1, xv.x * wB0));
        const float c2 = fmaf(xv.z, wC2, fmaf(xv.y, wC1, xv.x * wC0));
        const float c3 = fmaf(xv.z, wD2, fmaf(xv.y, wD1, xv.x * wD0));
        m0 = p0 ? c0 : fmaf(BETA, m0, c0);
        m1 = p1 ? c1 : fmaf(BETA, m1, c1);
        m2 = p2 ? c2 : fmaf(BETA, m2, c2);
        m3 = p3 ? c3 : fmaf(BETA, m3, c3);
        p0 = m0 > THRESH; p1 = m1 > THRESH;
        p2 = m2 > THRESH; p3 = m3 > THRESH;
        float4 sp;
        sp.x = p0 ? 1.0f : 0.0f;
        sp.y = p1 ? 1.0f : 0.0f;
        sp.z = p2 ? 1.0f : 0.0f;
        sp.w = p3 ? 1.0f : 0.0f;
        __stcs(out + (size_t)t * (BH / 4), sp);

        float q0 = sp.x * w2o0.x; q0 = fmaf(sp.y, w2o0.y, q0);
        q0 = fmaf(sp.z, w2o0.z, q0); q0 = fmaf(sp.w, w2o0.w, q0);
        float q1 = sp.x * w2o1.x; q1 = fmaf(sp.y, w2o1.y, q1);
        q1 = fmaf(sp.z, w2o1.z, q1); q1 = fmaf(sp.w, w2o1.w, q1);
        acc[2 * k + 0] = q0;
        acc[2 * k + 1] = q1;
    }

    // warp reduce the 20 partials, lane0 writes scratch
    #pragma unroll
    for (int j = 0; j < 20; ++j) {
        #pragma unroll
        for (int off = 16; off > 0; off >>= 1)
            acc[j] += __shfl_xor_sync(0xFFFFFFFFu, acc[j], off);
    }
    if (lane == 0) {
        #pragma unroll
        for (int j = 0; j < 20; ++j) g_partials[wj * 20 + j] = acc[j];
    }
}

// ---------------------------------------------------------------------------
// Kernel B: finish the readout. 256 blocks x 32 threads (one warp per b).
// Lanes 0..19 each sum the 4 quad-partials for one (t,o) (fixed order ->
// deterministic); lanes 0..1 then do the sigmoid-mean.
// ---------------------------------------------------------------------------
__global__ __launch_bounds__(32)
void snn_readout_kernel(float* __restrict__ avg_out)   // [B, 2]
{
    __shared__ float tot[20];
    const int b    = blockIdx.x;
    const int lane = threadIdx.x;

    if (lane < 20) {
        float s = 0.0f;
        #pragma unroll
        for (int q = 0; q < 4; ++q)
            s += g_partials[(4 * b + q) * 20 + lane];
        tot[lane] = s;
    }
    __syncthreads();

    if (lane < NOUT) {
        float s = 0.0f;
        #pragma unroll
        for (int k = 0; k < 10; ++k)
            s += 1.0f / (1.0f + expf(-tot[2 * k + lane]));
        avg_out[b * NOUT + lane] = s * 0.1f;
    }
}

// ---------------------------------------------------------------------------
extern "C" void kernel_launch(void* const* d_in, const int* in_sizes, int n_in,
                              void* d_out, int out_size)
{
    const float* x  = (const float*)d_in[0];   // [1000, 256, 3]
    const float* W1 = (const float*)d_in[1];   // [512, 3]
    const float* W2 = (const float*)d_in[2];   // [2, 512]
    float* out = (float*)d_out;

    float* spk_out = out;                      // 131,072,000 floats
    float* avg_out = out + SPK_ELEMS;          // 512 floats

    snn_scan_kernel<<<NJOBS, 32>>>(x, W1, W2, spk_out);
    snn_readout_kernel<<<BATCH, 32>>>(avg_out);
}

// round 9
// speedup vs baseline: 1.2005x; 1.0825x over previous
#include <cuda_runtime.h>
#include <cuda_bf16.h>

// Problem constants
#define T_STEPS 1000
#define T_MAIN  990            // readout tail covers [990, 1000)
#define BATCH   256
#define HID     512
#define NIN     3
#define NOUT    2
#define BH      (BATCH * HID)             // 131072
#define SPK_ELEMS ((size_t)T_STEPS * BH)  // 131,072,000

#define BETA    0.8f
#define THRESH  1.0f

// ---------------------------------------------------------------------------
// Single fused kernel (R3 layout + lockstep store bursts).
// Grid: 256 blocks (one per batch element b). 128 threads; each thread owns
// 4 consecutive hidden units h = tid*4..tid*4+3 -> STG.128 spike stores, so
// the block writes one contiguous 2KB row slice per timestep. A
// __syncthreads() every 8 steps keeps the 4 warps in lockstep so each 2KB
// slice is written as a temporally-coherent burst (HBM row locality).
// Readout over the last 10 steps is fused: register partials + block reduce.
// ---------------------------------------------------------------------------
__global__ __launch_bounds__(128)
void snn_fused_kernel(const float* __restrict__ x,     // [T, B, 3]
                      const float* __restrict__ W1,    // [512, 3]
                      const float* __restrict__ W2,    // [2, 512]
                      float* __restrict__ spk_out,     // [T, B, 512]
                      float* __restrict__ avg_out)     // [B, 2]
{
    __shared__ float sx[T_STEPS * 4];   // 16 KB, x rows padded 3 -> 4
    __shared__ float red[4][20];
    __shared__ float tot[20];

    const int b    = blockIdx.x;
    const int tid  = threadIdx.x;
    const int lane = tid & 31;
    const int wid  = tid >> 5;
    const int h0   = tid * 4;

    // Stage x[:, b, :] into shared (3000 scalar loads over 128 threads)
    for (int idx = tid; idx < T_STEPS * NIN; idx += 128) {
        const int t = idx / 3;
        const int i = idx - t * 3;
        sx[t * 4 + i] = x[(size_t)t * (BATCH * NIN) + b * NIN + i];
    }
    __syncthreads();

    // W1 rows for the 4 owned hidden units: 12 contiguous floats, 16B aligned
    const float4 w1a = reinterpret_cast<const float4*>(W1 + h0 * 3)[0];
    const float4 w1b = reinterpret_cast<const float4*>(W1 + h0 * 3)[1];
    const float4 w1c = reinterpret_cast<const float4*>(W1 + h0 * 3)[2];
    const float wA0 = w1a.x, wA1 = w1a.y, wA2 = w1a.z;
    const float wB0 = w1a.w, wB1 = w1b.x, wB2 = w1b.y;
    const float wC0 = w1b.z, wC1 = w1b.w, wC2 = w1c.x;
    const float wD0 = w1c.y, wD1 = w1c.z, wD2 = w1c.w;

    const float4* __restrict__ sx4 = reinterpret_cast<const float4*>(sx);
    float4* __restrict__ out = reinterpret_cast<float4*>(spk_out + (size_t)b * HID + h0);

    float m0 = 0.0f, m1 = 0.0f, m2 = 0.0f, m3 = 0.0f;
    bool  p0 = false, p1 = false, p2 = false, p3 = false;  // reset preds (prev mem)

    // ---- main scan: t in [0, 990), barrier every 8 steps ----
    for (int tb = 0; tb < T_MAIN; tb += 8) {
        #pragma unroll
        for (int u = 0; u < 8; ++u) {
            const int t = tb + u;
            if (t >= T_MAIN) break;     // tb=984 block runs 6 steps
            const float4 xv = sx4[t];
            const float c0 = fmaf(xv.z, wA2, fmaf(xv.y, wA1, xv.x * wA0));
            const float c1 = fmaf(xv.z, wB2, fmaf(xv.y, wB1, xv.x * wB0));
            const float c2 = fmaf(xv.z, wC2, fmaf(xv.y, wC1, xv.x * wC0));
            const float c3 = fmaf(xv.z, wD2, fmaf(xv.y, wD1, xv.x * wD0));
            // exact reference: mem_new = (beta*mem + cur) * (1 - reset_prev)
            m0 = p0 ? 0.0f : fmaf(BETA, m0, c0);
            m1 = p1 ? 0.0f : fmaf(BETA, m1, c1);
            m2 = p2 ? 0.0f : fmaf(BETA, m2, c2);
            m3 = p3 ? 0.0f : fmaf(BETA, m3, c3);
            // (reset -> mem=0 this step; next step integrates from 0)
            p0 = m0 > THRESH; p1 = m1 > THRESH;
            p2 = m2 > THRESH; p3 = m3 > THRESH;
            float4 sp;
            sp.x = p0 ? 1.0f : 0.0f;
            sp.y = p1 ? 1.0f : 0.0f;
            sp.z = p2 ? 1.0f : 0.0f;
            sp.w = p3 ? 1.0f : 0.0f;
            __stcs(out + (size_t)t * (BH / 4), sp);   // streaming STG.128
        }
        __syncthreads();   // keep the block's 2KB/t write bursts coherent
    }

    // ---- tail: t in [990, 1000), store spikes + accumulate readout ----
    const float4 w2o0 = reinterpret_cast<const float4*>(W2 + h0)[0];
    const float4 w2o1 = reinterpret_cast<const float4*>(W2 + HID + h0)[0];
    float acc[20];

    #pragma unroll
    for (int k = 0; k < 10; ++k) {
        const int t = T_MAIN + k;
        const float4 xv = sx4[t];
        const float c0 = fmaf(xv.z, wA2, fmaf(xv.y, wA1, xv.x * wA0));
        const float c1 = fmaf(xv.z, wB2, fmaf(xv.y, wB1, xv.x * wB0));
        const float c2 = fmaf(xv.z, wC2, fmaf(xv.y, wC1, xv.x * wC0));
        const float c3 = fmaf(xv.z, wD2, fmaf(xv.y, wD1, xv.x * wD0));
        m0 = p0 ? 0.0f : fmaf(BETA, m0, c0);
        m1 = p1 ? 0.0f : fmaf(BETA, m1, c1);
        m2 = p2 ? 0.0f : fmaf(BETA, m2, c2);
        m3 = p3 ? 0.0f : fmaf(BETA, m3, c3);
        p0 = m0 > THRESH; p1 = m1 > THRESH;
        p2 = m2 > THRESH; p3 = m3 > THRESH;
        float4 sp;
        sp.x = p0 ? 1.0f : 0.0f;
        sp.y = p1 ? 1.0f : 0.0f;
        sp.z = p2 ? 1.0f : 0.0f;
        sp.w = p3 ? 1.0f : 0.0f;
        __stcs(out + (size_t)t * (BH / 4), sp);

        float q0 = sp.x * w2o0.x; q0 = fmaf(sp.y, w2o0.y, q0);
        q0 = fmaf(sp.z, w2o0.z, q0); q0 = fmaf(sp.w, w2o0.w, q0);
        float q1 = sp.x * w2o1.x; q1 = fmaf(sp.y, w2o1.y, q1);
        q1 = fmaf(sp.z, w2o1.z, q1); q1 = fmaf(sp.w, w2o1.w, q1);
        acc[2 * k + 0] = q0;
        acc[2 * k + 1] = q1;
    }

    // ---- block reduction of the 20 partials ----
    #pragma unroll
    for (int j = 0; j < 20; ++j) {
        #pragma unroll
        for (int off = 16; off > 0; off >>= 1)
            acc[j] += __shfl_xor_sync(0xFFFFFFFFu, acc[j], off);
    }
    if (lane == 0) {
        #pragma unroll
        for (int j = 0; j < 20; ++j) red[wid][j] = acc[j];
    }
    __syncthreads();

    if (tid < 20)
        tot[tid] = red[0][tid] + red[1][tid] + red[2][tid] + red[3][tid];
    __syncthreads();

    if (tid < NOUT) {
        float s = 0.0f;
        #pragma unroll
        for (int k = 0; k < 10; ++k) {
            const float z = tot[2 * k + tid];
            s += 1.0f / (1.0f + expf(-z));
        }
        avg_out[b * NOUT + tid] = s * 0.1f;
    }
}

// ---------------------------------------------------------------------------
extern "C" void kernel_launch(void* const* d_in, const int* in_sizes, int n_in,
                              void* d_out, int out_size)
{
    const float* x  = (const float*)d_in[0];   // [1000, 256, 3]
    const float* W1 = (const float*)d_in[1];   // [512, 3]
    const float* W2 = (const float*)d_in[2];   // [2, 512]
    float* out = (float*)d_out;

    float* spk_out = out;                      // 131,072,000 floats
    float* avg_out = out + SPK_ELEMS;          // 512 floats

    snn_fused_kernel<<<BATCH, 128>>>(x, W1, W2, spk_out, avg_out);
}